// round 9
// baseline (speedup 1.0000x reference)
#include <cuda_runtime.h>
#include <cuda_bf16.h>
#include <math.h>
#include <stdint.h>

#define B_   512
#define D_   512
#define C_   50000
#define S_   30.0f
#define MARG 0.2f
#define EPS_ 1e-12f
#define NEG_INF_F (-3.402823466e38f)

#define BM   128
#define BN   128
#define KB   64                       // k-chunk: 64 bf16 = 128B
#define NKIT (D_ / KB)                // 8
#define NT2  ((C_ + BN - 1) / BN)     // 391
#define TPER 8                        // class tiles per CTA
#define NTG  ((NT2 + TPER - 1) / TPER) // 49

// smem: A resident 128KB + 4-stage B ring (16KB each) = 192KB
#define OFF_A    0
#define A_BYTES  (BM * D_ * 2)        // 131072
#define STG_B    16384
#define SMEM_SZ  (A_BYTES + 4 * STG_B)  // 196608

// ---------------- scratch (device globals) ----------------
__device__ __align__(16) __nv_bfloat16 g_Wn[(size_t)C_ * D_];   // normalized W, bf16
__device__ __align__(16) __nv_bfloat16 g_Ab[(2 * B_) * D_];     // [emb ; nm_W[y]] bf16
__device__ float  g_inv_norm[C_];
__device__ float  g_tcos[B_];                 // exact fp32 emb_i . nm_W[y_i]
__device__ float2 g_lse_part[B_][NT2];
__device__ double g_inter, g_ce;

// ---------------- helpers ----------------
__device__ __forceinline__ uint32_t smem_u32(const void* p) {
    uint32_t a;
    asm("{ .reg .u64 t; cvta.to.shared.u64 t, %1; cvt.u32.u64 %0, t; }" : "=r"(a) : "l"(p));
    return a;
}
__device__ __forceinline__ void cp16(uint32_t saddr, const void* gaddr) {
    asm volatile("cp.async.cg.shared.global [%0], [%1], 16;" :: "r"(saddr), "l"(gaddr));
}
__device__ __forceinline__ void cp_commit() { asm volatile("cp.async.commit_group;"); }
template <int N> __device__ __forceinline__ void cp_wait() {
    asm volatile("cp.async.wait_group %0;" :: "n"(N) : "memory");
}
__device__ __forceinline__ void ldmx4(uint32_t* r, uint32_t addr) {
    asm volatile("ldmatrix.sync.aligned.m8n8.x4.shared.b16 {%0,%1,%2,%3}, [%4];"
                 : "=r"(r[0]), "=r"(r[1]), "=r"(r[2]), "=r"(r[3]) : "r"(addr));
}
__device__ __forceinline__ void mma_bf16(float* c, const uint32_t* a, const uint32_t* b) {
    asm volatile(
        "mma.sync.aligned.m16n8k16.row.col.f32.bf16.bf16.f32 "
        "{%0,%1,%2,%3}, {%4,%5,%6,%7}, {%8,%9}, {%0,%1,%2,%3};\n"
        : "+f"(c[0]), "+f"(c[1]), "+f"(c[2]), "+f"(c[3])
        : "r"(a[0]), "r"(a[1]), "r"(a[2]), "r"(a[3]), "r"(b[0]), "r"(b[1]));
}
__device__ __forceinline__ uint32_t pk2(float a, float b) {
    __nv_bfloat162 h = __floats2bfloat162_rn(a, b);
    return *reinterpret_cast<uint32_t*>(&h);
}

// ---------------- kernel 1: row norms + normalized bf16 W (single pass) ----------------
__global__ void k_normconv(const float* __restrict__ W) {
    int row  = blockIdx.x * 8 + (threadIdx.x >> 5);
    int lane = threadIdx.x & 31;
    if (blockIdx.x == 0 && threadIdx.x == 0) { g_inter = 0.0; g_ce = 0.0; }
    if (row >= C_) return;
    const float4* wr = (const float4*)(W + (size_t)row * D_);
    float4 v[4];
    float s = 0.f;
#pragma unroll
    for (int i = 0; i < 4; i++) {
        v[i] = wr[lane + i * 32];
        s += v[i].x * v[i].x + v[i].y * v[i].y + v[i].z * v[i].z + v[i].w * v[i].w;
    }
#pragma unroll
    for (int off = 16; off; off >>= 1) s += __shfl_xor_sync(0xffffffffu, s, off);
    float inv = rsqrtf(s);
    if (lane == 0) g_inv_norm[row] = inv;
    uint2* out = (uint2*)(g_Wn + (size_t)row * D_);
#pragma unroll
    for (int i = 0; i < 4; i++) {
        uint2 u;
        u.x = pk2(v[i].x * inv, v[i].y * inv);
        u.y = pk2(v[i].z * inv, v[i].w * inv);
        out[lane + i * 32] = u;
    }
}

// ---------------- kernel 2: A = [emb ; nm_W[y]] bf16 and exact fp32 tcos ----------------
__global__ void k_prep(const float* __restrict__ emb, const float* __restrict__ W,
                       const int* __restrict__ y) {
    int b = blockIdx.x;       // 0..1023
    int t = threadIdx.x;      // 128
    if (b < B_) {
        float4 e = ((const float4*)(emb + (size_t)b * D_))[t];
        uint2 u; u.x = pk2(e.x, e.y); u.y = pk2(e.z, e.w);
        ((uint2*)(g_Ab + (size_t)b * D_))[t] = u;
    } else {
        int i  = b - B_;
        int yi = y[i];
        ((uint2*)(g_Ab + (size_t)b * D_))[t] = ((const uint2*)(g_Wn + (size_t)yi * D_))[t];
        float inv = g_inv_norm[yi];
        float4 w = ((const float4*)(W + (size_t)yi * D_))[t];
        float4 e = ((const float4*)(emb + (size_t)i * D_))[t];
        float d = (e.x * w.x + e.y * w.y + e.z * w.z + e.w * w.w) * inv;
        __shared__ float red[128];
        red[t] = d; __syncthreads();
#pragma unroll
        for (int s = 64; s; s >>= 1) { if (t < s) red[t] += red[t + s]; __syncthreads(); }
        if (t == 0) g_tcos[i] = red[0];
    }
}

// ---------------- kernel 3: bf16 GEMM, A resident in smem, 8 class tiles per CTA ----
// grid (8, 49): blockIdx.x = row-block (0..3 emb, 4..7 ws), blockIdx.y = tile group.
// 256 threads = 8 warps in 4(m) x 2(n); warp tile 32x64 (identical math to 186us kernel).
__global__ __launch_bounds__(256, 1) void k_main(const int* __restrict__ y) {
    extern __shared__ __align__(1024) char smem[];
    const uint32_t sbase = smem_u32(smem);
    __shared__ float pm[BM][2], ps[BM][2];
    __shared__ float red[256];

    const int tid    = threadIdx.x;
    const int lane   = tid & 31;
    const int warp   = tid >> 5;
    const int warp_m = warp & 3;
    const int warp_n = warp >> 2;
    const int gid    = lane >> 2;
    const int ctg    = lane & 3;
    const int rb      = blockIdx.x;
    const int tg      = blockIdx.y;
    const int rowbase = rb * BM;
    const int tile0   = tg * TPER;
    const int ntile   = (NT2 - tile0 < TPER) ? (NT2 - tile0) : TPER;
    const int G       = ntile * NKIT;

    const uint32_t sA = sbase + OFF_A;
    uint32_t sB[4];
#pragma unroll
    for (int s = 0; s < 4; s++) sB[s] = sbase + A_BYTES + s * STG_B;

    // ---- A resident load: 128 rows x 512 bf16, pitch 1024B, chunk' = ch ^ (r&7) ----
    {
#pragma unroll
        for (int i = 0; i < 32; i++) {
            int u = tid + i * 256;
            int r = u >> 6, ch = u & 63;
            uint32_t sw = (uint32_t)(r * 1024 + ((ch ^ (r & 7)) << 4));
            cp16(sA + sw, (const char*)g_Ab + ((size_t)(rowbase + r) * D_) * 2 + ch * 16);
        }
        cp_commit();
    }

    // ---- B loader: global iteration g -> tile g/8, kb g%8, buffer g&3 ----
    auto load_B = [&](int g) {
        const int tt = tile0 + (g >> 3);
        if (tt >= NT2) { cp_commit(); return; }
        const int kb  = g & 7;
        const uint32_t buf = sB[g & 3];
#pragma unroll
        for (int i = 0; i < 4; i++) {
            int u = tid + i * 256;
            int r = u >> 3, c = u & 7;
            int cls = tt * BN + r; if (cls >= C_) cls = C_ - 1;
            uint32_t sw = (uint32_t)(r * 128 + ((c ^ (r & 7)) << 4));
            cp16(buf + sw, (const char*)g_Wn + ((size_t)cls * D_ + kb * KB) * 2 + c * 16);
        }
        cp_commit();
    };

    // ---- per-thread ldmatrix invariants (same as 186us kernel; A pitch now 1024B) ----
    uint32_t a_off[2], a_r7[2];
    const uint32_t a_chk = (uint32_t)(lane >> 4);
#pragma unroll
    for (int mt = 0; mt < 2; mt++) {
        int r = warp_m * 32 + mt * 16 + (lane & 15);
        a_off[mt] = (uint32_t)(r * 1024);
        a_r7[mt]  = (uint32_t)(r & 7);
    }
    uint32_t b_off[4], b_r7[4];
    const uint32_t b_chk = (uint32_t)((lane >> 3) & 1);
#pragma unroll
    for (int np = 0; np < 4; np++) {
        int r = warp_n * 64 + np * 16 + (lane & 7) + ((lane >> 4) << 3);
        b_off[np] = (uint32_t)(r * 128);
        b_r7[np]  = (uint32_t)(r & 7);
    }

    float acc[2][8][4];
#pragma unroll
    for (int i = 0; i < 2; i++)
#pragma unroll
        for (int j = 0; j < 8; j++)
#pragma unroll
            for (int q = 0; q < 4; q++) acc[i][j][q] = 0.f;

    float local_inter = 0.f;

    // prologue: first 3 B tiles in flight (after the A group)
    load_B(0); load_B(1); load_B(2);

#pragma unroll 1
    for (int g = 0; g < G; g++) {
        const int kb  = g & 7;
        const uint32_t bbuf = sB[g & 3];

        cp_wait<2>();           // B group g complete (A older, also complete)
        __syncthreads();
        load_B(g + 3);          // post-sync: ring distance 3 (mod 4) => race-free

        const uint32_t a_col = (uint32_t)(kb * 128);
#pragma unroll
        for (int k16 = 0; k16 < 4; k16++) {
            const uint32_t c0 = 2 * k16;
            uint32_t af[2][4];
#pragma unroll
            for (int mt = 0; mt < 2; mt++)
                ldmx4(af[mt], sA + a_off[mt] + a_col + (((c0 + a_chk) ^ a_r7[mt]) << 4));
#pragma unroll
            for (int np = 0; np < 4; np++) {
                uint32_t bf[4];
                ldmx4(bf, bbuf + b_off[np] + (((c0 + b_chk) ^ b_r7[np]) << 4));
                mma_bf16(acc[0][2 * np],     af[0], bf);
                mma_bf16(acc[0][2 * np + 1], af[0], bf + 2);
                mma_bf16(acc[1][2 * np],     af[1], bf);
                mma_bf16(acc[1][2 * np + 1], af[1], bf + 2);
            }
        }

        if (kb == 7) {
            // ---------------- per-tile epilogue ----------------
            const int tile    = tile0 + (g >> 3);
            const int colbase = tile * BN;
            if (rb < 4) {
#pragma unroll
                for (int mt = 0; mt < 2; mt++) {
#pragma unroll
                    for (int h = 0; h < 2; h++) {
                        const int rloc = warp_m * 32 + mt * 16 + gid + h * 8;
                        const int r    = rowbase + rloc;
                        const int yr   = y[r];
                        float l[16];
                        float m = NEG_INF_F;
#pragma unroll
                        for (int nt = 0; nt < 8; nt++) {
#pragma unroll
                            for (int cc = 0; cc < 2; cc++) {
                                const int col = colbase + warp_n * 64 + nt * 8 + 2 * ctg + cc;
                                float lg = S_ * acc[mt][nt][h * 2 + cc];
                                if (col == yr) lg -= S_ * MARG;
                                if (col >= C_) lg = NEG_INF_F;
                                l[nt * 2 + cc] = lg;
                                m = fmaxf(m, lg);
                            }
                        }
                        m = fmaxf(m, __shfl_xor_sync(0xffffffffu, m, 1));
                        m = fmaxf(m, __shfl_xor_sync(0xffffffffu, m, 2));
                        float s = 0.f;
#pragma unroll
                        for (int q = 0; q < 16; q++) s += __expf(l[q] - m);
                        s += __shfl_xor_sync(0xffffffffu, s, 1);
                        s += __shfl_xor_sync(0xffffffffu, s, 2);
                        if (ctg == 0) { pm[rloc][warp_n] = m; ps[rloc][warp_n] = s; }
                    }
                }
                __syncthreads();
                if (tid < BM) {
                    float m0 = pm[tid][0], m1 = pm[tid][1];
                    float m  = fmaxf(m0, m1);
                    float s  = ps[tid][0] * __expf(m0 - m) + ps[tid][1] * __expf(m1 - m);
                    g_lse_part[rowbase + tid][tile] = make_float2(m, s);
                }
            } else {
#pragma unroll
                for (int mt = 0; mt < 2; mt++) {
#pragma unroll
                    for (int h = 0; h < 2; h++) {
                        const int rloc = warp_m * 32 + mt * 16 + gid + h * 8;
                        const int yr   = y[(rb - 4) * BM + rloc];
#pragma unroll
                        for (int nt = 0; nt < 8; nt++) {
#pragma unroll
                            for (int cc = 0; cc < 2; cc++) {
                                const int col = colbase + warp_n * 64 + nt * 8 + 2 * ctg + cc;
                                if (col < C_ && col != yr) {
                                    float gg = acc[mt][nt][h * 2 + cc];
                                    float d2 = fmaxf(2.f - 2.f * gg, EPS_);
                                    local_inter += __fdividef(1.f, d2);
                                }
                            }
                        }
                    }
                }
            }
            // reset accumulators for next tile
#pragma unroll
            for (int i = 0; i < 2; i++)
#pragma unroll
                for (int j = 0; j < 8; j++)
#pragma unroll
                    for (int q = 0; q < 4; q++) acc[i][j][q] = 0.f;
        }
    }

    if (rb >= 4) {
        red[tid] = local_inter; __syncthreads();
#pragma unroll
        for (int s = 128; s; s >>= 1) { if (tid < s) red[tid] += red[tid + s]; __syncthreads(); }
        if (tid == 0) atomicAdd(&g_inter, (double)red[0]);
    }
}

// ---------------- kernel 4a: per-row LSE combine + CE accumulate ----------------
__global__ void k_final1() {
    const int row = blockIdx.x;       // 0..511
    const int t   = threadIdx.x;      // 64
    float m = NEG_INF_F, s = 0.f;
    for (int j = t; j < NT2; j += 64) {
        float2 p = g_lse_part[row][j];
        float mn = fmaxf(m, p.x);
        s = s * __expf(m - mn) + p.y * __expf(p.x - mn);
        m = mn;
    }
#pragma unroll
    for (int off = 16; off; off >>= 1) {
        float om = __shfl_xor_sync(0xffffffffu, m, off);
        float os = __shfl_xor_sync(0xffffffffu, s, off);
        float mn = fmaxf(m, om);
        s = s * __expf(m - mn) + os * __expf(om - mn);
        m = mn;
    }
    __shared__ float sm[2], ss[2];
    if ((t & 31) == 0) { sm[t >> 5] = m; ss[t >> 5] = s; }
    __syncthreads();
    if (t == 0) {
        float mn = fmaxf(sm[0], sm[1]);
        float st = ss[0] * __expf(sm[0] - mn) + ss[1] * __expf(sm[1] - mn);
        float lse = mn + logf(st);
        float ce  = lse - S_ * (g_tcos[row] - MARG);
        atomicAdd(&g_ce, (double)ce);
    }
}

// ---------------- kernel 4b: write scalar ----------------
__global__ void k_final2(float* __restrict__ out) {
    out[0] = (float)(g_ce / (double)B_ + g_inter / ((double)B_ * (double)(C_ - 1)));
}

// ---------------- launch ----------------
extern "C" void kernel_launch(void* const* d_in, const int* in_sizes, int n_in,
                              void* d_out, int out_size) {
    const float* emb = nullptr;
    const float* W   = nullptr;
    const int*   y   = nullptr;
    for (int i = 0; i < n_in; i++) {
        if (in_sizes[i] == C_ * D_)      W   = (const float*)d_in[i];
        else if (in_sizes[i] == B_ * D_) emb = (const float*)d_in[i];
        else if (in_sizes[i] == B_)      y   = (const int*)d_in[i];
    }

    cudaFuncSetAttribute(k_main, cudaFuncAttributeMaxDynamicSharedMemorySize, SMEM_SZ);

    k_normconv<<<C_ / 8, 256>>>(W);
    k_prep<<<2 * B_, 128>>>(emb, W, y);
    k_main<<<dim3(8, NTG), 256, SMEM_SZ>>>(y);
    k_final1<<<B_, 64>>>();
    k_final2<<<1, 1>>>((float*)d_out);
}

// round 10
// speedup vs baseline: 1.3514x; 1.3514x over previous
#include <cuda_runtime.h>
#include <cuda_bf16.h>
#include <math.h>
#include <stdint.h>

#define B_   512
#define D_   512
#define C_   50000
#define S_   30.0f
#define MARG 0.2f
#define EPS_ 1e-12f
#define NEG_INF_F (-3.402823466e38f)

#define BM   128
#define BN   128
#define KB   64                       // k-chunk: 64 bf16 = 128B row pitch
#define NKIT (D_ / KB)                // 8
#define NT2  ((C_ + BN - 1) / BN)     // 391

#define SMEM_SZ 98304                 // 3 stages x (A 16KB + B 16KB)

// ---------------- scratch (device globals) ----------------
__device__ __align__(16) __nv_bfloat16 g_Wn[(size_t)C_ * D_];   // normalized W, bf16
__device__ __align__(16) __nv_bfloat16 g_Ab[(2 * B_) * D_];     // [emb ; nm_W[y]] bf16
__device__ float  g_inv_norm[C_];
__device__ float  g_tcos[B_];                 // exact fp32 emb_i . nm_W[y_i]
__device__ float2 g_lse_part[B_][NT2];
__device__ double g_inter, g_ce;

// ---------------- helpers ----------------
__device__ __forceinline__ uint32_t smem_u32(const void* p) {
    uint32_t a;
    asm("{ .reg .u64 t; cvta.to.shared.u64 t, %1; cvt.u32.u64 %0, t; }" : "=r"(a) : "l"(p));
    return a;
}
__device__ __forceinline__ void cp16(uint32_t saddr, const void* gaddr) {
    asm volatile("cp.async.cg.shared.global [%0], [%1], 16;" :: "r"(saddr), "l"(gaddr));
}
__device__ __forceinline__ void cp_commit() { asm volatile("cp.async.commit_group;"); }
template <int N> __device__ __forceinline__ void cp_wait() {
    asm volatile("cp.async.wait_group %0;" :: "n"(N) : "memory");
}
__device__ __forceinline__ void ldmx4(uint32_t* r, uint32_t addr) {
    asm volatile("ldmatrix.sync.aligned.m8n8.x4.shared.b16 {%0,%1,%2,%3}, [%4];"
                 : "=r"(r[0]), "=r"(r[1]), "=r"(r[2]), "=r"(r[3]) : "r"(addr));
}
__device__ __forceinline__ void mma_bf16(float* c, const uint32_t* a, const uint32_t* b) {
    asm volatile(
        "mma.sync.aligned.m16n8k16.row.col.f32.bf16.bf16.f32 "
        "{%0,%1,%2,%3}, {%4,%5,%6,%7}, {%8,%9}, {%0,%1,%2,%3};\n"
        : "+f"(c[0]), "+f"(c[1]), "+f"(c[2]), "+f"(c[3])
        : "r"(a[0]), "r"(a[1]), "r"(a[2]), "r"(a[3]), "r"(b[0]), "r"(b[1]));
}
__device__ __forceinline__ uint32_t pk2(float a, float b) {
    __nv_bfloat162 h = __floats2bfloat162_rn(a, b);
    return *reinterpret_cast<uint32_t*>(&h);
}

// ---------------- kernel 1: row norms + normalized bf16 W (single pass) ----------------
__global__ void k_normconv(const float* __restrict__ W) {
    int row  = blockIdx.x * 8 + (threadIdx.x >> 5);
    int lane = threadIdx.x & 31;
    if (blockIdx.x == 0 && threadIdx.x == 0) { g_inter = 0.0; g_ce = 0.0; }
    if (row >= C_) return;
    const float4* wr = (const float4*)(W + (size_t)row * D_);
    float4 v[4];
    float s = 0.f;
#pragma unroll
    for (int i = 0; i < 4; i++) {
        v[i] = wr[lane + i * 32];
        s += v[i].x * v[i].x + v[i].y * v[i].y + v[i].z * v[i].z + v[i].w * v[i].w;
    }
#pragma unroll
    for (int off = 16; off; off >>= 1) s += __shfl_xor_sync(0xffffffffu, s, off);
    float inv = rsqrtf(s);
    if (lane == 0) g_inv_norm[row] = inv;
    uint2* out = (uint2*)(g_Wn + (size_t)row * D_);
#pragma unroll
    for (int i = 0; i < 4; i++) {
        uint2 u;
        u.x = pk2(v[i].x * inv, v[i].y * inv);
        u.y = pk2(v[i].z * inv, v[i].w * inv);
        out[lane + i * 32] = u;
    }
}

// ---------------- kernel 2: A = [emb ; nm_W[y]] bf16 and exact fp32 tcos ----------------
__global__ void k_prep(const float* __restrict__ emb, const float* __restrict__ W,
                       const int* __restrict__ y) {
    int b = blockIdx.x;       // 0..1023
    int t = threadIdx.x;      // 128
    if (b < B_) {
        float4 e = ((const float4*)(emb + (size_t)b * D_))[t];
        uint2 u; u.x = pk2(e.x, e.y); u.y = pk2(e.z, e.w);
        ((uint2*)(g_Ab + (size_t)b * D_))[t] = u;
    } else {
        int i  = b - B_;
        int yi = y[i];
        ((uint2*)(g_Ab + (size_t)b * D_))[t] = ((const uint2*)(g_Wn + (size_t)yi * D_))[t];
        float inv = g_inv_norm[yi];
        float4 w = ((const float4*)(W + (size_t)yi * D_))[t];
        float4 e = ((const float4*)(emb + (size_t)i * D_))[t];
        float d = (e.x * w.x + e.y * w.y + e.z * w.z + e.w * w.w) * inv;
        __shared__ float red[128];
        red[t] = d; __syncthreads();
#pragma unroll
        for (int s = 64; s; s >>= 1) { if (t < s) red[t] += red[t + s]; __syncthreads(); }
        if (t == 0) g_tcos[i] = red[0];
    }
}

// ---------------- kernel 3: bf16 tensor-core GEMM + fused epilogues ----------------
// grid (8, 391): blockIdx.x = row-block (0..3 emb, 4..7 ws), blockIdx.y = class tile.
// 256 threads = 8 warps in 4(m) x 2(n); warp tile 32x64.
// 3-stage cp.async ring, ONE __syncthreads per iteration (load issued post-sync,
// ring distance 2 => write target was consumed in iteration kb-1).
__global__ __launch_bounds__(256, 2) void k_main(const int* __restrict__ y) {
    extern __shared__ __align__(1024) char smem[];
    const uint32_t sbase = smem_u32(smem);
    __shared__ float pm[BM][2], ps[BM][2];
    __shared__ float red[256];

    const int tid    = threadIdx.x;
    const int lane   = tid & 31;
    const int warp   = tid >> 5;
    const int warp_m = warp & 3;
    const int warp_n = warp >> 2;
    const int gid    = lane >> 2;
    const int ctg    = lane & 3;
    const int rb      = blockIdx.x;
    const int tile    = blockIdx.y;
    const int rowbase = rb * BM;
    const int colbase = tile * BN;

    uint32_t sA[3], sB[3];
#pragma unroll
    for (int s = 0; s < 3; s++) {
        sA[s] = sbase + s * 32768;
        sB[s] = sA[s] + 16384;
    }

    // ---- gmem -> smem loader (bf16, 16B cp.async, XOR-swizzled 128B rows) ----
    auto load_tile = [&](int kb, int buf) {
#pragma unroll
        for (int i = 0; i < 4; i++) {                 // A: 1024 16B units
            int u = tid + i * 256;
            int r = u >> 3, c = u & 7;
            uint32_t sw = (uint32_t)(r * 128 + ((c ^ (r & 7)) << 4));
            cp16(sA[buf] + sw,
                 (const char*)g_Ab + ((size_t)(rowbase + r) * D_ + kb * KB) * 2 + c * 16);
        }
#pragma unroll
        for (int i = 0; i < 4; i++) {                 // B: 1024 16B units
            int u = tid + i * 256;
            int r = u >> 3, c = u & 7;
            int cls = colbase + r; if (cls >= C_) cls = C_ - 1;
            uint32_t sw = (uint32_t)(r * 128 + ((c ^ (r & 7)) << 4));
            cp16(sB[buf] + sw,
                 (const char*)g_Wn + ((size_t)cls * D_ + kb * KB) * 2 + c * 16);
        }
        cp_commit();
    };

    // ---- per-thread ldmatrix address invariants (identical to the 186us kernel) ----
    uint32_t a_off[2], a_r7[2];
    const uint32_t a_chk = (uint32_t)(lane >> 4);
#pragma unroll
    for (int mt = 0; mt < 2; mt++) {
        int r = warp_m * 32 + mt * 16 + (lane & 15);
        a_off[mt] = (uint32_t)(r * 128);
        a_r7[mt]  = (uint32_t)(r & 7);
    }
    uint32_t b_off[4], b_r7[4];
    const uint32_t b_chk = (uint32_t)((lane >> 3) & 1);
#pragma unroll
    for (int np = 0; np < 4; np++) {
        int r = warp_n * 64 + np * 16 + (lane & 7) + ((lane >> 4) << 3);
        b_off[np] = (uint32_t)(r * 128);
        b_r7[np]  = (uint32_t)(r & 7);
    }

    float acc[2][8][4];
#pragma unroll
    for (int i = 0; i < 2; i++)
#pragma unroll
        for (int j = 0; j < 8; j++)
#pragma unroll
            for (int q = 0; q < 4; q++) acc[i][j][q] = 0.f;

    // ---- 3-stage pipelined mainloop (8 iterations, single sync each) ----
    load_tile(0, 0); load_tile(1, 1);
#pragma unroll 1
    for (int kb = 0; kb < NKIT; kb++) {
        const int b = kb % 3;
        cp_wait<1>();                     // stage kb's group complete
        __syncthreads();                  // all warps done with stage (kb-1)%3 == (kb+2)%3
        if (kb + 2 < NKIT) load_tile(kb + 2, (kb + 2) % 3);
        else               cp_commit();   // empty group keeps wait count aligned

#pragma unroll
        for (int k16 = 0; k16 < 4; k16++) {
            const uint32_t c0 = 2 * k16;
            uint32_t af[2][4];
#pragma unroll
            for (int mt = 0; mt < 2; mt++)
                ldmx4(af[mt], sA[b] + a_off[mt] + (((c0 + a_chk) ^ a_r7[mt]) << 4));
#pragma unroll
            for (int np = 0; np < 4; np++) {
                uint32_t bf[4];
                ldmx4(bf, sB[b] + b_off[np] + (((c0 + b_chk) ^ b_r7[np]) << 4));
                mma_bf16(acc[0][2 * np],     af[0], bf);
                mma_bf16(acc[0][2 * np + 1], af[0], bf + 2);
                mma_bf16(acc[1][2 * np],     af[1], bf);
                mma_bf16(acc[1][2 * np + 1], af[1], bf + 2);
            }
        }
    }
    __syncthreads();

    // ---------------- epilogue ----------------
    // acc[mt][nt][h*2+cc] = D[warp_m*32+mt*16+gid+h*8][warp_n*64+nt*8+2*ctg+cc]
    if (rb < 4) {
#pragma unroll
        for (int mt = 0; mt < 2; mt++) {
#pragma unroll
            for (int h = 0; h < 2; h++) {
                const int rloc = warp_m * 32 + mt * 16 + gid + h * 8;
                const int r    = rowbase + rloc;
                const int yr   = y[r];
                float l[16];
                float m = NEG_INF_F;
#pragma unroll
                for (int nt = 0; nt < 8; nt++) {
#pragma unroll
                    for (int cc = 0; cc < 2; cc++) {
                        const int col = colbase + warp_n * 64 + nt * 8 + 2 * ctg + cc;
                        float lg = S_ * acc[mt][nt][h * 2 + cc];
                        if (col == yr) lg -= S_ * MARG;
                        if (col >= C_) lg = NEG_INF_F;
                        l[nt * 2 + cc] = lg;
                        m = fmaxf(m, lg);
                    }
                }
                m = fmaxf(m, __shfl_xor_sync(0xffffffffu, m, 1));
                m = fmaxf(m, __shfl_xor_sync(0xffffffffu, m, 2));
                float s = 0.f;
#pragma unroll
                for (int q = 0; q < 16; q++) s += __expf(l[q] - m);
                s += __shfl_xor_sync(0xffffffffu, s, 1);
                s += __shfl_xor_sync(0xffffffffu, s, 2);
                if (ctg == 0) { pm[rloc][warp_n] = m; ps[rloc][warp_n] = s; }
            }
        }
        __syncthreads();
        if (tid < BM) {
            float m0 = pm[tid][0], m1 = pm[tid][1];
            float m  = fmaxf(m0, m1);
            float s  = ps[tid][0] * __expf(m0 - m) + ps[tid][1] * __expf(m1 - m);
            g_lse_part[rowbase + tid][tile] = make_float2(m, s);
        }
    } else {
        float local = 0.f;
#pragma unroll
        for (int mt = 0; mt < 2; mt++) {
#pragma unroll
            for (int h = 0; h < 2; h++) {
                const int rloc = warp_m * 32 + mt * 16 + gid + h * 8;
                const int yr   = y[(rb - 4) * BM + rloc];
#pragma unroll
                for (int nt = 0; nt < 8; nt++) {
#pragma unroll
                    for (int cc = 0; cc < 2; cc++) {
                        const int col = colbase + warp_n * 64 + nt * 8 + 2 * ctg + cc;
                        if (col < C_ && col != yr) {
                            float g  = acc[mt][nt][h * 2 + cc];
                            float d2 = fmaxf(2.f - 2.f * g, EPS_);
                            local += __fdividef(1.f, d2);
                        }
                    }
                }
            }
        }
        red[tid] = local; __syncthreads();
#pragma unroll
        for (int s = 128; s; s >>= 1) { if (tid < s) red[tid] += red[tid + s]; __syncthreads(); }
        if (tid == 0) atomicAdd(&g_inter, (double)red[0]);
    }
}

// ---------------- kernel 4a: per-row LSE combine + CE accumulate ----------------
__global__ void k_final1() {
    const int row = blockIdx.x;       // 0..511
    const int t   = threadIdx.x;      // 64
    float m = NEG_INF_F, s = 0.f;
    for (int j = t; j < NT2; j += 64) {
        float2 p = g_lse_part[row][j];
        float mn = fmaxf(m, p.x);
        s = s * __expf(m - mn) + p.y * __expf(p.x - mn);
        m = mn;
    }
#pragma unroll
    for (int off = 16; off; off >>= 1) {
        float om = __shfl_xor_sync(0xffffffffu, m, off);
        float os = __shfl_xor_sync(0xffffffffu, s, off);
        float mn = fmaxf(m, om);
        s = s * __expf(m - mn) + os * __expf(om - mn);
        m = mn;
    }
    __shared__ float sm[2], ss[2];
    if ((t & 31) == 0) { sm[t >> 5] = m; ss[t >> 5] = s; }
    __syncthreads();
    if (t == 0) {
        float mn = fmaxf(sm[0], sm[1]);
        float st = ss[0] * __expf(sm[0] - mn) + ss[1] * __expf(sm[1] - mn);
        float lse = mn + logf(st);
        float ce  = lse - S_ * (g_tcos[row] - MARG);
        atomicAdd(&g_ce, (double)ce);
    }
}

// ---------------- kernel 4b: write scalar ----------------
__global__ void k_final2(float* __restrict__ out) {
    out[0] = (float)(g_ce / (double)B_ + g_inter / ((double)B_ * (double)(C_ - 1)));
}

// ---------------- launch ----------------
extern "C" void kernel_launch(void* const* d_in, const int* in_sizes, int n_in,
                              void* d_out, int out_size) {
    const float* emb = nullptr;
    const float* W   = nullptr;
    const int*   y   = nullptr;
    for (int i = 0; i < n_in; i++) {
        if (in_sizes[i] == C_ * D_)      W   = (const float*)d_in[i];
        else if (in_sizes[i] == B_ * D_) emb = (const float*)d_in[i];
        else if (in_sizes[i] == B_)      y   = (const int*)d_in[i];
    }

    cudaFuncSetAttribute(k_main, cudaFuncAttributeMaxDynamicSharedMemorySize, SMEM_SZ);

    k_normconv<<<C_ / 8, 256>>>(W);
    k_prep<<<2 * B_, 128>>>(emb, W, y);
    k_main<<<dim3(8, NT2), 256, SMEM_SZ>>>(y);
    k_final1<<<B_, 64>>>();
    k_final2<<<1, 1>>>((float*)d_out);
}

// round 11
// speedup vs baseline: 1.3814x; 1.0221x over previous
#include <cuda_runtime.h>
#include <cuda_bf16.h>
#include <math.h>
#include <stdint.h>

#define B_   512
#define D_   512
#define C_   50000
#define S_   30.0f
#define MARG 0.2f
#define EPS_ 1e-12f
#define NEG_INF_F (-3.402823466e38f)

#define BM   128
#define BN   128
#define KB   64                       // k-chunk: 64 bf16 = 128B row pitch
#define NKIT (D_ / KB)                // 8
#define NT2  ((C_ + BN - 1) / BN)     // 391

#define SMEM_SZ 65536                 // 2 x (A 16KB + B 16KB)

// ---------------- scratch (device globals) ----------------
__device__ __align__(16) __nv_bfloat16 g_Wn[(size_t)C_ * D_];   // normalized W, bf16
__device__ __align__(16) __nv_bfloat16 g_Ab[(2 * B_) * D_];     // [emb ; nm_W[y]] bf16
__device__ float  g_inv_norm[C_];
__device__ float  g_tcos[B_];                 // exact fp32 emb_i . nm_W[y_i]
__device__ float2 g_lse_part[B_][NT2];
__device__ double g_inter, g_ce;

// ---------------- helpers ----------------
__device__ __forceinline__ uint32_t smem_u32(const void* p) {
    uint32_t a;
    asm("{ .reg .u64 t; cvta.to.shared.u64 t, %1; cvt.u32.u64 %0, t; }" : "=r"(a) : "l"(p));
    return a;
}
__device__ __forceinline__ void cp16(uint32_t saddr, const void* gaddr) {
    asm volatile("cp.async.cg.shared.global [%0], [%1], 16;" :: "r"(saddr), "l"(gaddr));
}
__device__ __forceinline__ void cp_commit() { asm volatile("cp.async.commit_group;"); }
template <int N> __device__ __forceinline__ void cp_wait() {
    asm volatile("cp.async.wait_group %0;" :: "n"(N) : "memory");
}
__device__ __forceinline__ void ldmx4(uint32_t* r, uint32_t addr) {
    asm volatile("ldmatrix.sync.aligned.m8n8.x4.shared.b16 {%0,%1,%2,%3}, [%4];"
                 : "=r"(r[0]), "=r"(r[1]), "=r"(r[2]), "=r"(r[3]) : "r"(addr));
}
__device__ __forceinline__ void mma_bf16(float* c, const uint32_t* a, const uint32_t* b) {
    asm volatile(
        "mma.sync.aligned.m16n8k16.row.col.f32.bf16.bf16.f32 "
        "{%0,%1,%2,%3}, {%4,%5,%6,%7}, {%8,%9}, {%0,%1,%2,%3};\n"
        : "+f"(c[0]), "+f"(c[1]), "+f"(c[2]), "+f"(c[3])
        : "r"(a[0]), "r"(a[1]), "r"(a[2]), "r"(a[3]), "r"(b[0]), "r"(b[1]));
}
__device__ __forceinline__ uint32_t pk2(float a, float b) {
    __nv_bfloat162 h = __floats2bfloat162_rn(a, b);
    return *reinterpret_cast<uint32_t*>(&h);
}

// ---------------- kernel 1: row norms + normalized bf16 W (single pass) ----------------
__global__ void k_normconv(const float* __restrict__ W) {
    int row  = blockIdx.x * 8 + (threadIdx.x >> 5);
    int lane = threadIdx.x & 31;
    if (blockIdx.x == 0 && threadIdx.x == 0) { g_inter = 0.0; g_ce = 0.0; }
    if (row >= C_) return;
    const float4* wr = (const float4*)(W + (size_t)row * D_);
    float4 v[4];
    float s = 0.f;
#pragma unroll
    for (int i = 0; i < 4; i++) {
        v[i] = wr[lane + i * 32];
        s += v[i].x * v[i].x + v[i].y * v[i].y + v[i].z * v[i].z + v[i].w * v[i].w;
    }
#pragma unroll
    for (int off = 16; off; off >>= 1) s += __shfl_xor_sync(0xffffffffu, s, off);
    float inv = rsqrtf(s);
    if (lane == 0) g_inv_norm[row] = inv;
    uint2* out = (uint2*)(g_Wn + (size_t)row * D_);
#pragma unroll
    for (int i = 0; i < 4; i++) {
        uint2 u;
        u.x = pk2(v[i].x * inv, v[i].y * inv);
        u.y = pk2(v[i].z * inv, v[i].w * inv);
        out[lane + i * 32] = u;
    }
}

// ---------------- kernel 2: A = [emb ; nm_W[y]] bf16 and exact fp32 tcos ----------------
__global__ void k_prep(const float* __restrict__ emb, const float* __restrict__ W,
                       const int* __restrict__ y) {
    int b = blockIdx.x;       // 0..1023
    int t = threadIdx.x;      // 128
    if (b < B_) {
        float4 e = ((const float4*)(emb + (size_t)b * D_))[t];
        uint2 u; u.x = pk2(e.x, e.y); u.y = pk2(e.z, e.w);
        ((uint2*)(g_Ab + (size_t)b * D_))[t] = u;
    } else {
        int i  = b - B_;
        int yi = y[i];
        ((uint2*)(g_Ab + (size_t)b * D_))[t] = ((const uint2*)(g_Wn + (size_t)yi * D_))[t];
        float inv = g_inv_norm[yi];
        float4 w = ((const float4*)(W + (size_t)yi * D_))[t];
        float4 e = ((const float4*)(emb + (size_t)i * D_))[t];
        float d = (e.x * w.x + e.y * w.y + e.z * w.z + e.w * w.w) * inv;
        __shared__ float red[128];
        red[t] = d; __syncthreads();
#pragma unroll
        for (int s = 64; s; s >>= 1) { if (t < s) red[t] += red[t + s]; __syncthreads(); }
        if (t == 0) g_tcos[i] = red[0];
    }
}

// ---------------- probe: empty launch to shift ncu's captured-launch index onto k_main ----
__global__ void k_probe() {}

// ---------------- kernel 3: bf16 tensor-core GEMM + fused epilogues (R6 winner, exact) ----
// grid (8, 391): blockIdx.x = row-block (0..3 emb, 4..7 ws), blockIdx.y = class tile.
// 256 threads = 8 warps in 4(m) x 2(n); warp tile 32x64. 2-stage cp.async pipeline.
__global__ __launch_bounds__(256, 2) void k_main(const int* __restrict__ y) {
    extern __shared__ __align__(1024) char smem[];
    const uint32_t sbase = smem_u32(smem);
    __shared__ float pm[BM][2], ps[BM][2];
    __shared__ float red[256];

    const int tid    = threadIdx.x;
    const int lane   = tid & 31;
    const int warp   = tid >> 5;
    const int warp_m = warp & 3;
    const int warp_n = warp >> 2;
    const int gid    = lane >> 2;
    const int ctg    = lane & 3;
    const int rb      = blockIdx.x;
    const int tile    = blockIdx.y;
    const int rowbase = rb * BM;
    const int colbase = tile * BN;

    const uint32_t sA[2] = { sbase,          sbase + 16384 };
    const uint32_t sB[2] = { sbase + 32768,  sbase + 49152 };

    // ---- gmem -> smem loader (bf16, 16B cp.async, XOR-swizzled 128B rows) ----
    auto load_tile = [&](int kb, int buf) {
#pragma unroll
        for (int i = 0; i < 4; i++) {                 // A: 1024 16B units
            int u = tid + i * 256;
            int r = u >> 3, c = u & 7;
            uint32_t sw = (uint32_t)(r * 128 + ((c ^ (r & 7)) << 4));
            cp16(sA[buf] + sw,
                 (const char*)g_Ab + ((size_t)(rowbase + r) * D_ + kb * KB) * 2 + c * 16);
        }
#pragma unroll
        for (int i = 0; i < 4; i++) {                 // B: 1024 16B units
            int u = tid + i * 256;
            int r = u >> 3, c = u & 7;
            int cls = colbase + r; if (cls >= C_) cls = C_ - 1;
            uint32_t sw = (uint32_t)(r * 128 + ((c ^ (r & 7)) << 4));
            cp16(sB[buf] + sw,
                 (const char*)g_Wn + ((size_t)cls * D_ + kb * KB) * 2 + c * 16);
        }
        cp_commit();
    };

    // ---- per-thread ldmatrix address invariants ----
    uint32_t a_off[2], a_r7[2];
    const uint32_t a_chk = (uint32_t)(lane >> 4);
#pragma unroll
    for (int mt = 0; mt < 2; mt++) {
        int r = warp_m * 32 + mt * 16 + (lane & 15);
        a_off[mt] = (uint32_t)(r * 128);
        a_r7[mt]  = (uint32_t)(r & 7);
    }
    uint32_t b_off[4], b_r7[4];
    const uint32_t b_chk = (uint32_t)((lane >> 3) & 1);
#pragma unroll
    for (int np = 0; np < 4; np++) {
        int r = warp_n * 64 + np * 16 + (lane & 7) + ((lane >> 4) << 3);
        b_off[np] = (uint32_t)(r * 128);
        b_r7[np]  = (uint32_t)(r & 7);
    }

    float acc[2][8][4];
#pragma unroll
    for (int i = 0; i < 2; i++)
#pragma unroll
        for (int j = 0; j < 8; j++)
#pragma unroll
            for (int q = 0; q < 4; q++) acc[i][j][q] = 0.f;

    // ---- double-buffered mainloop ----
    load_tile(0, 0);
#pragma unroll 1
    for (int kb = 0; kb < NKIT; kb++) {
        const int b = kb & 1;
        if (kb + 1 < NKIT) { load_tile(kb + 1, b ^ 1); cp_wait<1>(); }
        else               { cp_wait<0>(); }
        __syncthreads();

#pragma unroll
        for (int k16 = 0; k16 < 4; k16++) {
            const uint32_t c0 = 2 * k16;
            uint32_t af[2][4];
#pragma unroll
            for (int mt = 0; mt < 2; mt++)
                ldmx4(af[mt], sA[b] + a_off[mt] + (((c0 + a_chk) ^ a_r7[mt]) << 4));
#pragma unroll
            for (int np = 0; np < 4; np++) {
                uint32_t bf[4];
                ldmx4(bf, sB[b] + b_off[np] + (((c0 + b_chk) ^ b_r7[np]) << 4));
                mma_bf16(acc[0][2 * np],     af[0], bf);
                mma_bf16(acc[0][2 * np + 1], af[0], bf + 2);
                mma_bf16(acc[1][2 * np],     af[1], bf);
                mma_bf16(acc[1][2 * np + 1], af[1], bf + 2);
            }
        }
        __syncthreads();
    }

    // ---------------- epilogue ----------------
    // acc[mt][nt][h*2+cc] = D[warp_m*32+mt*16+gid+h*8][warp_n*64+nt*8+2*ctg+cc]
    if (rb < 4) {
#pragma unroll
        for (int mt = 0; mt < 2; mt++) {
#pragma unroll
            for (int h = 0; h < 2; h++) {
                const int rloc = warp_m * 32 + mt * 16 + gid + h * 8;
                const int r    = rowbase + rloc;
                const int yr   = y[r];
                float l[16];
                float m = NEG_INF_F;
#pragma unroll
                for (int nt = 0; nt < 8; nt++) {
#pragma unroll
                    for (int cc = 0; cc < 2; cc++) {
                        const int col = colbase + warp_n * 64 + nt * 8 + 2 * ctg + cc;
                        float lg = S_ * acc[mt][nt][h * 2 + cc];
                        if (col == yr) lg -= S_ * MARG;
                        if (col >= C_) lg = NEG_INF_F;
                        l[nt * 2 + cc] = lg;
                        m = fmaxf(m, lg);
                    }
                }
                m = fmaxf(m, __shfl_xor_sync(0xffffffffu, m, 1));
                m = fmaxf(m, __shfl_xor_sync(0xffffffffu, m, 2));
                float s = 0.f;
#pragma unroll
                for (int q = 0; q < 16; q++) s += __expf(l[q] - m);
                s += __shfl_xor_sync(0xffffffffu, s, 1);
                s += __shfl_xor_sync(0xffffffffu, s, 2);
                if (ctg == 0) { pm[rloc][warp_n] = m; ps[rloc][warp_n] = s; }
            }
        }
        __syncthreads();
        if (tid < BM) {
            float m0 = pm[tid][0], m1 = pm[tid][1];
            float m  = fmaxf(m0, m1);
            float s  = ps[tid][0] * __expf(m0 - m) + ps[tid][1] * __expf(m1 - m);
            g_lse_part[rowbase + tid][tile] = make_float2(m, s);
        }
    } else {
        float local = 0.f;
#pragma unroll
        for (int mt = 0; mt < 2; mt++) {
#pragma unroll
            for (int h = 0; h < 2; h++) {
                const int rloc = warp_m * 32 + mt * 16 + gid + h * 8;
                const int yr   = y[(rb - 4) * BM + rloc];
#pragma unroll
                for (int nt = 0; nt < 8; nt++) {
#pragma unroll
                    for (int cc = 0; cc < 2; cc++) {
                        const int col = colbase + warp_n * 64 + nt * 8 + 2 * ctg + cc;
                        if (col < C_ && col != yr) {
                            float g  = acc[mt][nt][h * 2 + cc];
                            float d2 = fmaxf(2.f - 2.f * g, EPS_);
                            local += __fdividef(1.f, d2);
                        }
                    }
                }
            }
        }
        red[tid] = local; __syncthreads();
#pragma unroll
        for (int s = 128; s; s >>= 1) { if (tid < s) red[tid] += red[tid + s]; __syncthreads(); }
        if (tid == 0) atomicAdd(&g_inter, (double)red[0]);
    }
}

// ---------------- kernel 4a: per-row LSE combine + CE accumulate (128 thr) ----------------
__global__ void k_final1() {
    const int row = blockIdx.x;       // 0..511
    const int t   = threadIdx.x;      // 128
    float m = NEG_INF_F, s = 0.f;
    for (int j = t; j < NT2; j += 128) {
        float2 p = g_lse_part[row][j];
        float mn = fmaxf(m, p.x);
        s = s * __expf(m - mn) + p.y * __expf(p.x - mn);
        m = mn;
    }
#pragma unroll
    for (int off = 16; off; off >>= 1) {
        float om = __shfl_xor_sync(0xffffffffu, m, off);
        float os = __shfl_xor_sync(0xffffffffu, s, off);
        float mn = fmaxf(m, om);
        s = s * __expf(m - mn) + os * __expf(om - mn);
        m = mn;
    }
    __shared__ float sm[4], ss[4];
    if ((t & 31) == 0) { sm[t >> 5] = m; ss[t >> 5] = s; }
    __syncthreads();
    if (t == 0) {
        float mn = fmaxf(fmaxf(sm[0], sm[1]), fmaxf(sm[2], sm[3]));
        float st = ss[0] * __expf(sm[0] - mn) + ss[1] * __expf(sm[1] - mn)
                 + ss[2] * __expf(sm[2] - mn) + ss[3] * __expf(sm[3] - mn);
        float lse = mn + logf(st);
        float ce  = lse - S_ * (g_tcos[row] - MARG);
        atomicAdd(&g_ce, (double)ce);
    }
}

// ---------------- kernel 4b: write scalar ----------------
__global__ void k_final2(float* __restrict__ out) {
    out[0] = (float)(g_ce / (double)B_ + g_inter / ((double)B_ * (double)(C_ - 1)));
}

// ---------------- launch ----------------
extern "C" void kernel_launch(void* const* d_in, const int* in_sizes, int n_in,
                              void* d_out, int out_size) {
    const float* emb = nullptr;
    const float* W   = nullptr;
    const int*   y   = nullptr;
    for (int i = 0; i < n_in; i++) {
        if (in_sizes[i] == C_ * D_)      W   = (const float*)d_in[i];
        else if (in_sizes[i] == B_ * D_) emb = (const float*)d_in[i];
        else if (in_sizes[i] == B_)      y   = (const int*)d_in[i];
    }

    cudaFuncSetAttribute(k_main, cudaFuncAttributeMaxDynamicSharedMemorySize, SMEM_SZ);

    k_normconv<<<C_ / 8, 256>>>(W);
    k_prep<<<2 * B_, 128>>>(emb, W, y);
    k_probe<<<1, 32>>>();              // shifts ncu's captured-launch slot onto k_main
    k_main<<<dim3(8, NT2), 256, SMEM_SZ>>>(y);
    k_final1<<<B_, 128>>>();
    k_final2<<<1, 1>>>((float*)d_out);
}